// round 12
// baseline (speedup 1.0000x reference)
#include <cuda_runtime.h>
#include <math.h>
#include <stdint.h>

// ---------------------------------------------------------------------------
// Scratch buffers
// ---------------------------------------------------------------------------
__device__ __align__(256) float g_bufX[16600000];   // padded input 64*5*258*200
__device__ __align__(256) float g_bufA[6400000];    // unpadded conv outputs
__device__ __align__(256) float g_bufB[7000000];    // padded activations
__device__ __align__(256) float g_bufC[7000000];    // padded activations
// tf32-split weights: L1@0(2048) L2@2048(8192) L3@10240(32768)
//                     L6@43008(589824) L7@632832(589824)  total 1222656
__device__ __align__(256) uint32_t g_bufWhi[1222656];
__device__ __align__(256) uint32_t g_bufWlo[1222656];

// ---------------------------------------------------------------------------
// tf32 helpers
// ---------------------------------------------------------------------------
__device__ __forceinline__ uint32_t f2tf32(float x) {
    uint32_t r;
    asm("cvt.rna.tf32.f32 %0, %1;" : "=r"(r) : "f"(x));
    return r;
}
__device__ __forceinline__ void tf32split(float x, uint32_t& hi, uint32_t& lo) {
    hi = f2tf32(x);
    float r = x - __uint_as_float(hi);
    lo = f2tf32(r);
}
__device__ __forceinline__ void mma_tf32(float d[4],
                                         uint32_t a0, uint32_t a1, uint32_t a2, uint32_t a3,
                                         uint32_t b0, uint32_t b1) {
    asm volatile(
        "mma.sync.aligned.m16n8k8.row.col.f32.tf32.tf32.f32 "
        "{%0,%1,%2,%3}, {%4,%5,%6,%7}, {%8,%9}, {%0,%1,%2,%3};"
        : "+f"(d[0]), "+f"(d[1]), "+f"(d[2]), "+f"(d[3])
        : "r"(a0), "r"(a1), "r"(a2), "r"(a3), "r"(b0), "r"(b1));
}

__global__ void split_one_kernel(const float* __restrict__ w,
                                 uint32_t* __restrict__ hi,
                                 uint32_t* __restrict__ lo, int n)
{
    int i = blockIdx.x * blockDim.x + threadIdx.x;
    if (i >= n) return;
    uint32_t h, l;
    tf32split(w[i], h, l);
    hi[i] = h;
    lo[i] = l;
}

// ---------------------------------------------------------------------------
// ALIGNED padded layout: left pad 4, right pad 4 -> WPa = W+8 (mult of 4).
// ---------------------------------------------------------------------------
template<int H, int W, int TB>
__global__ void __launch_bounds__(TB)
pad_copy_a(const float* __restrict__ src, float* __restrict__ dst)
{
    static_assert(W % 4 == 0, "");
    constexpr int WPa = W + 8;
    constexpr int HP  = H + 2;
    const float4* s4 = reinterpret_cast<const float4*>(src + (size_t)blockIdx.x * (H * W));
    float* d = dst + (size_t)blockIdx.x * (HP * WPa);

    for (int i = threadIdx.x; i < WPa; i += TB) {
        d[i] = 0.f;
        d[(HP - 1) * WPa + i] = 0.f;
    }
    for (int h = threadIdx.x; h < H; h += TB) {
        d[(h + 1) * WPa + 3] = 0.f;
        d[(h + 1) * WPa + W + 4] = 0.f;
    }
    constexpr int N4 = H * W / 4;
    for (int q = threadIdx.x; q < N4; q += TB) {
        int j = 4 * q;
        int h = j / W;
        int o = (h + 1) * WPa + 4 + (j - h * W);
        *reinterpret_cast<float4*>(d + o) = __ldg(s4 + q);
    }
}

// ---------------------------------------------------------------------------
// FFMA conv. LOFF = left offset of readable halo (3 aligned / 0 legacy).
// ---------------------------------------------------------------------------
template<int K, int S, int CIN, int HP, int WP, int LOFF,
         int COUT, int HOUT, int WOUT,
         int CO_T, int CI_T, int ZSPLIT, bool ATOMIC, bool BIAS, bool RELU>
__global__ void __launch_bounds__(256)
conv_tiled(const float* __restrict__ in,
           const float* __restrict__ w,
           const float* __restrict__ bias,
           float* __restrict__ out)
{
    constexpr int CO_M = 4, PIX_M = 4;
    constexpr int G    = CO_T / CO_M;
    constexpr int PTH  = 256 / G;
    constexpr int PIXB = PTH * PIX_M;
    constexpr int KK   = K * K;
    constexpr int WPITCH = CI_T * KK + 1;
    constexpr int HW   = HOUT * WOUT;
    constexpr int NT   = 64 * HW;
    constexpr int PSZ  = HP * WP;
    static_assert(CIN / ZSPLIT == CI_T, "one smem weight tile per block");

    __shared__ float sw[CO_T * WPITCH];

    const int tco  = threadIdx.x % G;
    const int tpix = threadIdx.x / G;
    const int co0  = blockIdx.y * CO_T;
    const int nbase = blockIdx.x * PIXB;
    const int ci_begin = blockIdx.z * CI_T;

    {
        const int tot = CO_T * CI_T * KK;
        const float* wsrc = w + ((long)co0 * CIN + ci_begin) * KK;
        for (int idx = threadIdx.x; idx < tot; idx += 256) {
            int c = idx / (CI_T * KK);
            int r = idx % (CI_T * KK);
            sw[c * WPITCH + r] = wsrc[(long)c * CIN * KK + r];
        }
    }
    __syncthreads();

    int nidx[PIX_M];
    const float* pci[PIX_M];
    #pragma unroll
    for (int p = 0; p < PIX_M; p++) {
        int n = nbase + p * PTH + tpix;
        nidx[p] = n;
        int nn = (n < NT) ? n : 0;
        int b  = nn / HW;
        int hw = nn % HW;
        int ho = hw / WOUT, wo = hw % WOUT;
        pci[p] = in + ((long)b * CIN + ci_begin) * PSZ + (ho * S) * WP + (wo * S) + LOFF;
    }

    float acc[CO_M][PIX_M];
    #pragma unroll
    for (int m = 0; m < CO_M; m++)
        #pragma unroll
        for (int p = 0; p < PIX_M; p++) acc[m][p] = 0.f;

    const float* wrow0 = &sw[(tco * CO_M) * WPITCH];
    for (int ci = 0; ci < CI_T; ci++) {
        const float* wrow = wrow0 + ci * KK;
        #pragma unroll
        for (int kh = 0; kh < K; kh++) {
            #pragma unroll
            for (int kw = 0; kw < K; kw++) {
                float iv[PIX_M];
                #pragma unroll
                for (int p = 0; p < PIX_M; p++)
                    iv[p] = __ldg(pci[p] + kh * WP + kw);
                float wv[CO_M];
                #pragma unroll
                for (int m = 0; m < CO_M; m++)
                    wv[m] = wrow[m * WPITCH + kh * K + kw];
                #pragma unroll
                for (int m = 0; m < CO_M; m++)
                    #pragma unroll
                    for (int p = 0; p < PIX_M; p++)
                        acc[m][p] = fmaf(wv[m], iv[p], acc[m][p]);
            }
        }
        #pragma unroll
        for (int p = 0; p < PIX_M; p++) pci[p] += PSZ;
    }

    #pragma unroll
    for (int p = 0; p < PIX_M; p++) {
        int n = nidx[p];
        if (n >= NT) continue;
        int b = n / HW, hw = n % HW;
        #pragma unroll
        for (int m = 0; m < CO_M; m++) {
            int co = co0 + tco * CO_M + m;
            long oidx = ((long)b * COUT + co) * HW + hw;
            if (ATOMIC) {
                atomicAdd(out + oidx, acc[m][p]);
            } else {
                float v = acc[m][p] + (BIAS ? bias[co] : 0.f);
                if (RELU) v = fmaxf(v, 0.f);
                out[oidx] = v;
            }
        }
    }
}

// ---------------------------------------------------------------------------
// Tensor-core conv, tf32 3x-split, pre-split weights. Optional K-split.
// ---------------------------------------------------------------------------
template<int K, int S, int CIN, int HP, int WP, int LOFF,
         int COUT, int HOUT, int WOUT, int NTILES, int ZSPLIT, bool ATOMIC>
__global__ void __launch_bounds__(256)
conv_mma(const float* __restrict__ in,
         const uint32_t* __restrict__ whi,
         const uint32_t* __restrict__ wlo,
         float* __restrict__ out)
{
    constexpr int KK    = K * K;
    constexpr int KTOT  = CIN * KK;
    constexpr int KSPAN = KTOT / ZSPLIT;
    constexpr int HW    = HOUT * WOUT;
    constexpr int PSZ   = HP * WP;
    static_assert(KSPAN % 8 == 0, "");

    const int warp = threadIdx.x >> 5;
    const int lane = threadIdx.x & 31;
    const int gid  = lane >> 2;
    const int tig  = lane & 3;

    const int co0   = blockIdx.y * 16;
    const int pix0  = (blockIdx.x * 8 + warp) * (NTILES * 8);
    const int kbase = blockIdx.z * KSPAN;

    const uint32_t* ph0 = whi + (size_t)(co0 + gid) * KTOT + kbase;
    const uint32_t* ph1 = ph0 + (size_t)8 * KTOT;
    const uint32_t* pl0 = wlo + (size_t)(co0 + gid) * KTOT + kbase;
    const uint32_t* pl1 = pl0 + (size_t)8 * KTOT;

    const float* pb[NTILES];
    #pragma unroll
    for (int t = 0; t < NTILES; t++) {
        int p  = pix0 + t * 8 + gid;
        int b  = p / HW, hw = p % HW;
        int ho = hw / WOUT, wo = hw % WOUT;
        pb[t] = in + (size_t)b * CIN * PSZ + (ho * S) * WP + (wo * S) + LOFF;
    }

    float d[NTILES][4];
    #pragma unroll
    for (int t = 0; t < NTILES; t++)
        #pragma unroll
        for (int i = 0; i < 4; i++) d[t][i] = 0.f;

    #pragma unroll 2
    for (int kc = 0; kc < KSPAN / 8; kc++) {
        const int k0 = kbase + kc * 8 + tig;
        const int k1 = k0 + 4;
        int ci0 = k0 / KK, t0 = k0 % KK;
        int ci1 = k1 / KK, t1 = k1 % KK;
        int off0 = ci0 * PSZ + (t0 / K) * WP + (t0 % K);
        int off1 = ci1 * PSZ + (t1 / K) * WP + (t1 % K);

        uint32_t ah0 = __ldg(ph0 + kc * 8 + tig);
        uint32_t ah2 = __ldg(ph0 + kc * 8 + tig + 4);
        uint32_t ah1 = __ldg(ph1 + kc * 8 + tig);
        uint32_t ah3 = __ldg(ph1 + kc * 8 + tig + 4);
        uint32_t al0 = __ldg(pl0 + kc * 8 + tig);
        uint32_t al2 = __ldg(pl0 + kc * 8 + tig + 4);
        uint32_t al1 = __ldg(pl1 + kc * 8 + tig);
        uint32_t al3 = __ldg(pl1 + kc * 8 + tig + 4);

        #pragma unroll
        for (int t = 0; t < NTILES; t++) {
            float b0 = __ldg(pb[t] + off0);
            float b1 = __ldg(pb[t] + off1);
            uint32_t bh0, bl0, bh1, bl1;
            tf32split(b0, bh0, bl0);
            tf32split(b1, bh1, bl1);
            mma_tf32(d[t], ah0, ah1, ah2, ah3, bh0, bh1);
            mma_tf32(d[t], ah0, ah1, ah2, ah3, bl0, bl1);
            mma_tf32(d[t], al0, al1, al2, al3, bh0, bh1);
        }
    }

    #pragma unroll
    for (int t = 0; t < NTILES; t++) {
        #pragma unroll
        for (int cc = 0; cc < 2; cc++) {
            int p  = pix0 + t * 8 + 2 * tig + cc;
            int b  = p / HW, hw = p % HW;
            long base = ((long)b * COUT) * HW + hw;
            long i0 = base + (long)(co0 + gid) * HW;
            long i1 = base + (long)(co0 + gid + 8) * HW;
            if (ATOMIC) {
                atomicAdd(out + i0, d[t][cc]);
                atomicAdd(out + i1, d[t][cc + 2]);
            } else {
                out[i0] = d[t][cc];
                out[i1] = d[t][cc + 2];
            }
        }
    }
}

// ---------------------------------------------------------------------------
// Single-pass register-resident instance norm -> ALIGNED padded output.
// ---------------------------------------------------------------------------
template<bool RELU, int H, int W, int TB>
__global__ void __launch_bounds__(TB)
inorm_pad_reg(const float* __restrict__ src, float* __restrict__ dst)
{
    static_assert(W % 4 == 0, "");
    constexpr int WPa = W + 8;
    constexpr int HP  = H + 2;
    constexpr int HW  = H * W;
    constexpr int N4  = HW / 4;
    static_assert(N4 % TB == 0, "exact tiling");
    constexpr int VPT = N4 / TB;
    constexpr int NW  = TB / 32;

    const float4* s4 = reinterpret_cast<const float4*>(src + (size_t)blockIdx.x * HW);
    float* d = dst + (size_t)blockIdx.x * (HP * WPa);

    float4 v[VPT];
    float sum = 0.f, ssq = 0.f;
    #pragma unroll
    for (int k = 0; k < VPT; k++) {
        float4 t = __ldg(s4 + threadIdx.x + k * TB);
        v[k] = t;
        sum += (t.x + t.y) + (t.z + t.w);
        ssq += t.x * t.x + t.y * t.y + t.z * t.z + t.w * t.w;
    }
    #pragma unroll
    for (int off = 16; off > 0; off >>= 1) {
        sum += __shfl_xor_sync(0xFFFFFFFFu, sum, off);
        ssq += __shfl_xor_sync(0xFFFFFFFFu, ssq, off);
    }
    __shared__ float shs[NW], shq[NW], fin[2];
    if ((threadIdx.x & 31) == 0) {
        shs[threadIdx.x >> 5] = sum;
        shq[threadIdx.x >> 5] = ssq;
    }
    __syncthreads();
    if (threadIdx.x == 0) {
        float s = 0.f, q = 0.f;
        #pragma unroll
        for (int i = 0; i < NW; i++) { s += shs[i]; q += shq[i]; }
        constexpr float invN = 1.0f / (float)HW;
        float m = s * invN;
        float var = q * invN - m * m;
        fin[0] = m;
        fin[1] = rsqrtf(var + 1e-5f);
    }
    __syncthreads();
    const float m = fin[0];
    const float r = fin[1];

    for (int i = threadIdx.x; i < WPa; i += TB) {
        d[i] = 0.f;
        d[(HP - 1) * WPa + i] = 0.f;
    }
    for (int h = threadIdx.x; h < H; h += TB) {
        d[(h + 1) * WPa + 3] = 0.f;
        d[(h + 1) * WPa + W + 4] = 0.f;
    }
    #pragma unroll
    for (int k = 0; k < VPT; k++) {
        int j = 4 * (threadIdx.x + k * TB);
        int h = j / W;
        int o = (h + 1) * WPa + 4 + (j - h * W);
        float4 t = v[k];
        t.x = (t.x - m) * r; t.y = (t.y - m) * r;
        t.z = (t.z - m) * r; t.w = (t.w - m) * r;
        if (RELU) {
            t.x = fmaxf(t.x, 0.f); t.y = fmaxf(t.y, 0.f);
            t.z = fmaxf(t.z, 0.f); t.w = fmaxf(t.w, 0.f);
        }
        *reinterpret_cast<float4*>(d + o) = t;
    }
}

// ---------------------------------------------------------------------------
// Warp-per-plane instance norm for small planes (legacy halo-1 layout).
// ---------------------------------------------------------------------------
template<bool RELU, int H, int W, int HP, int WP>
__global__ void inorm_pad_warp(const float* __restrict__ src,
                               float* __restrict__ dst, int nplane)
{
    constexpr int HW  = H * W;
    constexpr int TOT = HP * WP;
    int warp = (blockIdx.x * blockDim.x + threadIdx.x) >> 5;
    int lane = threadIdx.x & 31;
    if (warp >= nplane) return;
    const float* s = src + (size_t)warp * HW;
    float* d = dst + (size_t)warp * TOT;

    float sum = 0.f, ssq = 0.f;
    #pragma unroll
    for (int k = 0; k < (HW + 31) / 32; k++) {
        int i = lane + 32 * k;
        float v = (i < HW) ? __ldg(s + i) : 0.f;
        sum += v;
        ssq += v * v;
    }
    #pragma unroll
    for (int off = 16; off > 0; off >>= 1) {
        sum += __shfl_xor_sync(0xFFFFFFFFu, sum, off);
        ssq += __shfl_xor_sync(0xFFFFFFFFu, ssq, off);
    }
    constexpr float invN = 1.0f / (float)HW;
    float m = sum * invN;
    float var = ssq * invN - m * m;
    float r = rsqrtf(var + 1e-5f);

    #pragma unroll
    for (int k = 0; k < (TOT + 31) / 32; k++) {
        int i = lane + 32 * k;
        if (i < TOT) {
            int h = i / WP, w = i % WP;
            bool in = (h >= 1) && (h <= H) && (w >= 1) && (w <= W);
            float v = 0.f;
            if (in) {
                v = (__ldg(s + (h - 1) * W + (w - 1)) - m) * r;
                if (RELU) v = fmaxf(v, 0.f);
            }
            d[i] = v;
        }
    }
}

// ---------------------------------------------------------------------------
// FC1 with fused maxpool (reads legacy 6x5 padded planes).
// ---------------------------------------------------------------------------
__global__ void fc1_pool_kernel(const float* __restrict__ act,
                                const float* __restrict__ w,
                                const float* __restrict__ bias,
                                float* __restrict__ out)
{
    int b = blockIdx.x;
    int j = threadIdx.x;
    __shared__ float xs[512];
    for (int idx = threadIdx.x; idx < 512; idx += 128) {
        int i = idx & 1;
        int c = idx >> 1;
        const float* p = act + ((size_t)b * 256 + c) * 30;
        int r0 = (2 * i + 1) * 5 + 1;
        int r1 = (2 * i + 2) * 5 + 1;
        xs[idx] = fmaxf(fmaxf(__ldg(p + r0), __ldg(p + r0 + 1)),
                        fmaxf(__ldg(p + r1), __ldg(p + r1 + 1)));
    }
    __syncthreads();
    const float* wr = w + (size_t)j * 512;
    float acc = bias[j];
    #pragma unroll 8
    for (int k = 0; k < 512; k++)
        acc = fmaf(xs[k], __ldg(wr + k), acc);
    out[(size_t)b * 128 + j] = fmaxf(acc, 0.0f);
}

// ---------------------------------------------------------------------------
// FC2: (64,128) @ (50,128)^T + b, tanh -> d_out coor
// ---------------------------------------------------------------------------
__global__ void fc2_kernel(const float* __restrict__ in,
                           const float* __restrict__ w,
                           const float* __restrict__ bias,
                           float* __restrict__ out)
{
    int b = blockIdx.x;
    int j = threadIdx.x;
    if (j >= 50) return;
    const float* x  = in + (size_t)b * 128;
    const float* wr = w  + (size_t)j * 128;
    float acc = bias[j];
    #pragma unroll 8
    for (int k = 0; k < 128; k++)
        acc = fmaf(__ldg(x + k), __ldg(wr + k), acc);
    out[(size_t)b * 50 + j] = tanhf(acc);
}

// ---------------------------------------------------------------------------
// Loss kernel.
// ---------------------------------------------------------------------------
__global__ void loss_kernel(float* __restrict__ out)
{
    const float* pts = out;
    int b = threadIdx.x;
    const float* g = pts + (size_t)b * 50;
    #define G(i, j, comp) g[((i) * 5 + (j)) * 2 + (comp)]

    float rx = 0.f, ry = 0.f, cx = 0.f, cy = 0.f;
    for (int i = 0; i < 5; i++) {
        for (int s = 0; s < 3; s++) {
            #pragma unroll
            for (int comp = 0; comp < 2; comp++) {
                float a0 = G(i, s, comp), a1 = G(i, s + 1, comp), a2 = G(i, s + 2, comp);
                float d0 = (a1 - a0) * (a1 - a0);
                float d1 = (a2 - a1) * (a2 - a1);
                float rv = fmaxf(0.08f, fabsf(d1 - d0));
                if (comp == 0) rx += rv; else ry += rv;
                float c0 = G(s, i, comp), c1 = G(s + 1, i, comp), c2 = G(s + 2, i, comp);
                float e0 = (c1 - c0) * (c1 - c0);
                float e1 = (c2 - c1) * (c2 - c1);
                float cv = fmaxf(0.08f, fabsf(e1 - e0));
                if (comp == 0) cx += cv; else cy += cv;
            }
        }
    }

    __shared__ float sh[4][64];
    sh[0][b] = rx; sh[1][b] = ry; sh[2][b] = cx; sh[3][b] = cy;
    __syncthreads();
    for (int off = 32; off > 0; off >>= 1) {
        if (b < off) {
            sh[0][b] += sh[0][b + off];
            sh[1][b] += sh[1][b + off];
            sh[2][b] += sh[2][b + off];
            sh[3][b] += sh[3][b + off];
        }
        __syncthreads();
    }

    if (b == 0) {
        float inv = 1.0f / 960.0f;
        out[3200] = sh[0][0] * inv;
        out[3201] = sh[1][0] * inv;
        out[3202] = sh[2][0] * inv;
        out[3203] = sh[3][0] * inv;

        const float* g0 = pts;
        #define G0(i, j, comp) g0[((i) * 5 + (j)) * 2 + (comp)]
        float rg = 0.f, cg = 0.f;
        for (int i = 0; i < 5; i++) {
            for (int s = 0; s < 3; s++) {
                {
                    float x0 = G0(i, s, 0),     y0 = G0(i, s, 1);
                    float x1 = G0(i, s + 1, 0), y1 = G0(i, s + 1, 1);
                    float x2 = G0(i, s + 2, 0), y2 = G0(i, s + 2, 1);
                    rg += fabsf((y1 - y0) * (x1 - x2) - (y1 - y2) * (x1 - x0));
                }
                {
                    float x0 = G0(s, i, 0),     y0 = G0(s, i, 1);
                    float x1 = G0(s + 1, i, 0), y1 = G0(s + 1, i, 1);
                    float x2 = G0(s + 2, i, 0), y2 = G0(s + 2, i, 1);
                    cg += fabsf((y1 - y0) * (x1 - x2) - (y1 - y2) * (x1 - x0));
                }
            }
        }
        out[3204] = fmaxf(rg, 0.02f);
        out[3205] = fmaxf(cg, 0.02f);
    }
}

// ---------------------------------------------------------------------------
// Host-side orchestration
// ---------------------------------------------------------------------------
static inline int cdiv(int a, int b) { return (a + b - 1) / b; }

extern "C" void kernel_launch(void* const* d_in, const int* in_sizes, int n_in,
                              void* d_out, int out_size)
{
    (void)in_sizes; (void)n_in; (void)out_size;

    const float* x = (const float*)d_in[0];
    const float* W[8];
    const float* Bi[8];
    for (int i = 0; i < 8; i++) {
        W[i]  = (const float*)d_in[1 + 2 * i];
        Bi[i] = (const float*)d_in[2 + 2 * i];
    }
    const float* fc1_w = (const float*)d_in[17];
    const float* fc1_b = (const float*)d_in[18];
    const float* fc2_w = (const float*)d_in[19];
    const float* fc2_b = (const float*)d_in[20];
    float* out = (float*)d_out;

    float* X;  cudaGetSymbolAddress((void**)&X,  g_bufX);
    float* A;  cudaGetSymbolAddress((void**)&A,  g_bufA);
    float* Bb; cudaGetSymbolAddress((void**)&Bb, g_bufB);
    float* C;  cudaGetSymbolAddress((void**)&C,  g_bufC);
    uint32_t* Whi; cudaGetSymbolAddress((void**)&Whi, g_bufWhi);
    uint32_t* Wlo; cudaGetSymbolAddress((void**)&Wlo, g_bufWlo);

    // ---- pad input + pre-split weights for L1,L2,L3,L6,L7
    pad_copy_a<256, 192, 256><<<64 * 5, 256>>>(x, X);
    split_one_kernel<<<cdiv(2048, 256), 256>>>(W[1], Whi, Wlo, 2048);
    split_one_kernel<<<cdiv(8192, 256), 256>>>(W[2], Whi + 2048, Wlo + 2048, 8192);
    split_one_kernel<<<cdiv(32768, 256), 256>>>(W[3], Whi + 10240, Wlo + 10240, 32768);
    split_one_kernel<<<cdiv(589824, 256), 256>>>(W[6], Whi + 43008, Wlo + 43008, 589824);
    split_one_kernel<<<cdiv(589824, 256), 256>>>(W[7], Whi + 632832, Wlo + 632832, 589824);

    // ---- L0 (FFMA, aligned in): conv X->A [bias+relu], inorm A->Bb (130x104)
    {
        dim3 grid(64 * 128 * 96 / 512, 1, 1);
        conv_tiled<4, 2, 5, 258, 200, 3, 8, 128, 96, 8, 5, 1, false, true, true>
            <<<grid, 256>>>(X, W[0], Bi[0], A);
        inorm_pad_reg<false, 128, 96, 256><<<512, 256>>>(A, Bb);
    }
    // ---- L1 (MMA): Bb->A, inorm A->C (66x56)
    {
        conv_mma<4, 2, 8, 130, 104, 3, 16, 64, 48, 4, 1, false>
            <<<dim3(768, 1, 1), 256>>>(Bb, Whi, Wlo, A);
        inorm_pad_reg<true, 64, 48, 256><<<1024, 256>>>(A, C);
    }
    // ---- L2 (MMA): C->A, inorm A->Bb (34x32)
    {
        conv_mma<4, 2, 16, 66, 56, 3, 32, 32, 24, 4, 1, false>
            <<<dim3(192, 2, 1), 256>>>(C, Whi + 2048, Wlo + 2048, A);
        inorm_pad_reg<true, 32, 24, 64><<<2048, 64>>>(A, Bb);
    }
    // ---- L3 (MMA): Bb->A, inorm A->C (legacy 18x14)
    {
        conv_mma<4, 2, 32, 34, 32, 3, 64, 16, 12, 2, 1, false>
            <<<dim3(96, 4, 1), 256>>>(Bb, Whi + 10240, Wlo + 10240, A);
        inorm_pad_warp<true, 16, 12, 18, 14><<<512, 256>>>(A, C, 64 * 64);
    }
    // ---- L4 (FFMA, legacy in): Z=4 atomic; C->A, inorm A->Bb (10x8)
    {
        cudaMemsetAsync(A, 0, (size_t)64 * 128 * 8 * 6 * sizeof(float));
        dim3 grid(64 * 8 * 6 / 128, 4, 4);
        conv_tiled<4, 2, 64, 18, 14, 0, 128, 8, 6, 32, 16, 4, true, false, false>
            <<<grid, 256>>>(C, W[4], nullptr, A);
        inorm_pad_warp<true, 8, 6, 10, 8><<<1024, 256>>>(A, Bb, 64 * 128);
    }
    // ---- L5 (FFMA, legacy in): Z=8 atomic; Bb->A, inorm A->C (6x5)
    {
        cudaMemsetAsync(A, 0, (size_t)64 * 256 * 4 * 3 * sizeof(float));
        dim3 grid(6, 8, 8);
        conv_tiled<4, 2, 128, 10, 8, 0, 256, 4, 3, 32, 16, 8, true, false, false>
            <<<grid, 256>>>(Bb, W[5], nullptr, A);
        inorm_pad_warp<true, 4, 3, 6, 5><<<2048, 256>>>(A, C, 64 * 256);
    }
    // ---- L6 (MMA, legacy in 6x5): Z=4 atomic; C->A, inorm A->Bb
    {
        cudaMemsetAsync(A, 0, (size_t)64 * 256 * 4 * 3 * sizeof(float));
        conv_mma<3, 1, 256, 6, 5, 0, 256, 4, 3, 1, 4, true>
            <<<dim3(12, 16, 4), 256>>>(C, Whi + 43008, Wlo + 43008, A);
        inorm_pad_warp<true, 4, 3, 6, 5><<<2048, 256>>>(A, Bb, 64 * 256);
    }
    // ---- L7 (MMA, legacy in 6x5): Z=4 atomic; Bb->A, inorm A->C
    {
        cudaMemsetAsync(A, 0, (size_t)64 * 256 * 4 * 3 * sizeof(float));
        conv_mma<3, 1, 256, 6, 5, 0, 256, 4, 3, 1, 4, true>
            <<<dim3(12, 16, 4), 256>>>(Bb, Whi + 632832, Wlo + 632832, A);
        inorm_pad_warp<true, 4, 3, 6, 5><<<2048, 256>>>(A, C, 64 * 256);
    }

    // ---- fused maxpool + FC1: C (legacy padded) -> A (64,128)
    fc1_pool_kernel<<<64, 128>>>(C, fc1_w, fc1_b, A);
    // ---- FC2 + tanh: A -> out[0..3199]
    fc2_kernel<<<64, 64>>>(A, fc2_w, fc2_b, out);
    // ---- losses
    loss_kernel<<<1, 64>>>(out);
}

// round 13
// speedup vs baseline: 1.5150x; 1.5150x over previous
#include <cuda_runtime.h>
#include <math.h>
#include <stdint.h>

// ---------------------------------------------------------------------------
// Scratch buffers
// ---------------------------------------------------------------------------
__device__ __align__(256) float g_bufX[16600000];   // padded input 64*5*258*200
__device__ __align__(256) float g_bufA[6400000];    // unpadded conv outputs
__device__ __align__(256) float g_bufB[7000000];    // padded activations
__device__ __align__(256) float g_bufC[7000000];    // padded activations
__device__ __align__(256) uint32_t g_bufWhi[2048];  // L1 tf32-hi weights
__device__ __align__(256) uint32_t g_bufWlo[2048];  // L1 tf32-lo weights

// ---------------------------------------------------------------------------
// tf32 helpers
// ---------------------------------------------------------------------------
__device__ __forceinline__ uint32_t f2tf32(float x) {
    uint32_t r;
    asm("cvt.rna.tf32.f32 %0, %1;" : "=r"(r) : "f"(x));
    return r;
}
__device__ __forceinline__ void tf32split(float x, uint32_t& hi, uint32_t& lo) {
    hi = f2tf32(x);
    float r = x - __uint_as_float(hi);
    lo = f2tf32(r);
}
__device__ __forceinline__ void mma_tf32(float d[4],
                                         uint32_t a0, uint32_t a1, uint32_t a2, uint32_t a3,
                                         uint32_t b0, uint32_t b1) {
    asm volatile(
        "mma.sync.aligned.m16n8k8.row.col.f32.tf32.tf32.f32 "
        "{%0,%1,%2,%3}, {%4,%5,%6,%7}, {%8,%9}, {%0,%1,%2,%3};"
        : "+f"(d[0]), "+f"(d[1]), "+f"(d[2]), "+f"(d[3])
        : "r"(a0), "r"(a1), "r"(a2), "r"(a3), "r"(b0), "r"(b1));
}

__global__ void split_weights_kernel(const float* __restrict__ w1,
                                     uint32_t* __restrict__ hi,
                                     uint32_t* __restrict__ lo)
{
    int i = blockIdx.x * blockDim.x + threadIdx.x;
    if (i >= 2048) return;
    uint32_t h, l;
    tf32split(w1[i], h, l);
    hi[i] = h;
    lo[i] = l;
}

// ---------------------------------------------------------------------------
// ALIGNED padded layout: left pad 4, right pad 4 -> WPa = W+8 (mult of 4).
// ---------------------------------------------------------------------------
template<int H, int W, int TB>
__global__ void __launch_bounds__(TB)
pad_copy_a(const float* __restrict__ src, float* __restrict__ dst)
{
    static_assert(W % 4 == 0, "");
    constexpr int WPa = W + 8;
    constexpr int HP  = H + 2;
    const float4* s4 = reinterpret_cast<const float4*>(src + (size_t)blockIdx.x * (H * W));
    float* d = dst + (size_t)blockIdx.x * (HP * WPa);

    for (int i = threadIdx.x; i < WPa; i += TB) {
        d[i] = 0.f;
        d[(HP - 1) * WPa + i] = 0.f;
    }
    for (int h = threadIdx.x; h < H; h += TB) {
        d[(h + 1) * WPa + 3] = 0.f;
        d[(h + 1) * WPa + W + 4] = 0.f;
    }
    constexpr int N4 = H * W / 4;
    for (int q = threadIdx.x; q < N4; q += TB) {
        int j = 4 * q;
        int h = j / W;
        int o = (h + 1) * WPa + 4 + (j - h * W);
        *reinterpret_cast<float4*>(d + o) = __ldg(s4 + q);
    }
}

// ---------------------------------------------------------------------------
// FFMA conv. LOFF = left offset of readable halo (3 aligned / 0 legacy).
// ---------------------------------------------------------------------------
template<int K, int S, int CIN, int HP, int WP, int LOFF,
         int COUT, int HOUT, int WOUT,
         int CO_T, int CI_T, int ZSPLIT, bool ATOMIC, bool BIAS, bool RELU>
__global__ void __launch_bounds__(256)
conv_tiled(const float* __restrict__ in,
           const float* __restrict__ w,
           const float* __restrict__ bias,
           float* __restrict__ out)
{
    constexpr int CO_M = 4, PIX_M = 4;
    constexpr int G    = CO_T / CO_M;
    constexpr int PTH  = 256 / G;
    constexpr int PIXB = PTH * PIX_M;
    constexpr int KK   = K * K;
    constexpr int WPITCH = CI_T * KK + 1;
    constexpr int HW   = HOUT * WOUT;
    constexpr int NT   = 64 * HW;
    constexpr int PSZ  = HP * WP;
    static_assert(CIN / ZSPLIT == CI_T, "one smem weight tile per block");

    __shared__ float sw[CO_T * WPITCH];

    const int tco  = threadIdx.x % G;
    const int tpix = threadIdx.x / G;
    const int co0  = blockIdx.y * CO_T;
    const int nbase = blockIdx.x * PIXB;
    const int ci_begin = blockIdx.z * CI_T;

    {
        const int tot = CO_T * CI_T * KK;
        const float* wsrc = w + ((long)co0 * CIN + ci_begin) * KK;
        for (int idx = threadIdx.x; idx < tot; idx += 256) {
            int c = idx / (CI_T * KK);
            int r = idx % (CI_T * KK);
            sw[c * WPITCH + r] = wsrc[(long)c * CIN * KK + r];
        }
    }
    __syncthreads();

    int nidx[PIX_M];
    const float* pci[PIX_M];
    #pragma unroll
    for (int p = 0; p < PIX_M; p++) {
        int n = nbase + p * PTH + tpix;
        nidx[p] = n;
        int nn = (n < NT) ? n : 0;
        int b  = nn / HW;
        int hw = nn % HW;
        int ho = hw / WOUT, wo = hw % WOUT;
        pci[p] = in + ((long)b * CIN + ci_begin) * PSZ + (ho * S) * WP + (wo * S) + LOFF;
    }

    float acc[CO_M][PIX_M];
    #pragma unroll
    for (int m = 0; m < CO_M; m++)
        #pragma unroll
        for (int p = 0; p < PIX_M; p++) acc[m][p] = 0.f;

    const float* wrow0 = &sw[(tco * CO_M) * WPITCH];
    for (int ci = 0; ci < CI_T; ci++) {
        const float* wrow = wrow0 + ci * KK;
        #pragma unroll
        for (int kh = 0; kh < K; kh++) {
            #pragma unroll
            for (int kw = 0; kw < K; kw++) {
                float iv[PIX_M];
                #pragma unroll
                for (int p = 0; p < PIX_M; p++)
                    iv[p] = __ldg(pci[p] + kh * WP + kw);
                float wv[CO_M];
                #pragma unroll
                for (int m = 0; m < CO_M; m++)
                    wv[m] = wrow[m * WPITCH + kh * K + kw];
                #pragma unroll
                for (int m = 0; m < CO_M; m++)
                    #pragma unroll
                    for (int p = 0; p < PIX_M; p++)
                        acc[m][p] = fmaf(wv[m], iv[p], acc[m][p]);
            }
        }
        #pragma unroll
        for (int p = 0; p < PIX_M; p++) pci[p] += PSZ;
    }

    #pragma unroll
    for (int p = 0; p < PIX_M; p++) {
        int n = nidx[p];
        if (n >= NT) continue;
        int b = n / HW, hw = n % HW;
        #pragma unroll
        for (int m = 0; m < CO_M; m++) {
            int co = co0 + tco * CO_M + m;
            long oidx = ((long)b * COUT + co) * HW + hw;
            if (ATOMIC) {
                atomicAdd(out + oidx, acc[m][p]);
            } else {
                float v = acc[m][p] + (BIAS ? bias[co] : 0.f);
                if (RELU) v = fmaxf(v, 0.f);
                out[oidx] = v;
            }
        }
    }
}

// ---------------------------------------------------------------------------
// Tensor-core conv for L1, tf32 3x-split, pre-split weights. NTILES=8.
// ---------------------------------------------------------------------------
template<int K, int S, int CIN, int HP, int WP, int LOFF,
         int COUT, int HOUT, int WOUT, int NTILES>
__global__ void __launch_bounds__(256)
conv_mma(const float* __restrict__ in,
         const uint32_t* __restrict__ whi,
         const uint32_t* __restrict__ wlo,
         float* __restrict__ out)
{
    constexpr int KK    = K * K;
    constexpr int KTOT  = CIN * KK;
    constexpr int HW    = HOUT * WOUT;
    constexpr int PSZ   = HP * WP;

    const int warp = threadIdx.x >> 5;
    const int lane = threadIdx.x & 31;
    const int gid  = lane >> 2;
    const int tig  = lane & 3;

    const int co0  = blockIdx.y * 16;
    const int pix0 = (blockIdx.x * 8 + warp) * (NTILES * 8);

    const uint32_t* ph0 = whi + (size_t)(co0 + gid) * KTOT;
    const uint32_t* ph1 = ph0 + (size_t)8 * KTOT;
    const uint32_t* pl0 = wlo + (size_t)(co0 + gid) * KTOT;
    const uint32_t* pl1 = pl0 + (size_t)8 * KTOT;

    const float* pb[NTILES];
    #pragma unroll
    for (int t = 0; t < NTILES; t++) {
        int p  = pix0 + t * 8 + gid;
        int b  = p / HW, hw = p % HW;
        int ho = hw / WOUT, wo = hw % WOUT;
        pb[t] = in + (size_t)b * CIN * PSZ + (ho * S) * WP + (wo * S) + LOFF;
    }

    float d[NTILES][4];
    #pragma unroll
    for (int t = 0; t < NTILES; t++)
        #pragma unroll
        for (int i = 0; i < 4; i++) d[t][i] = 0.f;

    #pragma unroll 2
    for (int kc = 0; kc < KTOT / 8; kc++) {
        const int k0 = kc * 8 + tig;
        const int k1 = k0 + 4;
        int ci0 = k0 / KK, t0 = k0 % KK;
        int ci1 = k1 / KK, t1 = k1 % KK;
        int off0 = ci0 * PSZ + (t0 / K) * WP + (t0 % K);
        int off1 = ci1 * PSZ + (t1 / K) * WP + (t1 % K);

        uint32_t ah0 = __ldg(ph0 + k0);
        uint32_t ah2 = __ldg(ph0 + k1);
        uint32_t ah1 = __ldg(ph1 + k0);
        uint32_t ah3 = __ldg(ph1 + k1);
        uint32_t al0 = __ldg(pl0 + k0);
        uint32_t al2 = __ldg(pl0 + k1);
        uint32_t al1 = __ldg(pl1 + k0);
        uint32_t al3 = __ldg(pl1 + k1);

        #pragma unroll
        for (int t = 0; t < NTILES; t++) {
            float b0 = __ldg(pb[t] + off0);
            float b1 = __ldg(pb[t] + off1);
            uint32_t bh0, bl0, bh1, bl1;
            tf32split(b0, bh0, bl0);
            tf32split(b1, bh1, bl1);
            mma_tf32(d[t], ah0, ah1, ah2, ah3, bh0, bh1);
            mma_tf32(d[t], ah0, ah1, ah2, ah3, bl0, bl1);
            mma_tf32(d[t], al0, al1, al2, al3, bh0, bh1);
        }
    }

    #pragma unroll
    for (int t = 0; t < NTILES; t++) {
        #pragma unroll
        for (int cc = 0; cc < 2; cc++) {
            int p  = pix0 + t * 8 + 2 * tig + cc;
            int b  = p / HW, hw = p % HW;
            long base = ((long)b * COUT) * HW + hw;
            out[base + (long)(co0 + gid) * HW]     = d[t][cc];
            out[base + (long)(co0 + gid + 8) * HW] = d[t][cc + 2];
        }
    }
}

// ---------------------------------------------------------------------------
// Single-pass register-resident instance norm -> ALIGNED padded output.
// ---------------------------------------------------------------------------
template<bool RELU, int H, int W, int TB>
__global__ void __launch_bounds__(TB)
inorm_pad_reg(const float* __restrict__ src, float* __restrict__ dst)
{
    static_assert(W % 4 == 0, "");
    constexpr int WPa = W + 8;
    constexpr int HP  = H + 2;
    constexpr int HW  = H * W;
    constexpr int N4  = HW / 4;
    static_assert(N4 % TB == 0, "exact tiling");
    constexpr int VPT = N4 / TB;
    constexpr int NW  = TB / 32;

    const float4* s4 = reinterpret_cast<const float4*>(src + (size_t)blockIdx.x * HW);
    float* d = dst + (size_t)blockIdx.x * (HP * WPa);

    float4 v[VPT];
    float sum = 0.f, ssq = 0.f;
    #pragma unroll
    for (int k = 0; k < VPT; k++) {
        float4 t = __ldg(s4 + threadIdx.x + k * TB);
        v[k] = t;
        sum += (t.x + t.y) + (t.z + t.w);
        ssq += t.x * t.x + t.y * t.y + t.z * t.z + t.w * t.w;
    }
    #pragma unroll
    for (int off = 16; off > 0; off >>= 1) {
        sum += __shfl_xor_sync(0xFFFFFFFFu, sum, off);
        ssq += __shfl_xor_sync(0xFFFFFFFFu, ssq, off);
    }
    __shared__ float shs[NW], shq[NW], fin[2];
    if ((threadIdx.x & 31) == 0) {
        shs[threadIdx.x >> 5] = sum;
        shq[threadIdx.x >> 5] = ssq;
    }
    __syncthreads();
    if (threadIdx.x == 0) {
        float s = 0.f, q = 0.f;
        #pragma unroll
        for (int i = 0; i < NW; i++) { s += shs[i]; q += shq[i]; }
        constexpr float invN = 1.0f / (float)HW;
        float m = s * invN;
        float var = q * invN - m * m;
        fin[0] = m;
        fin[1] = rsqrtf(var + 1e-5f);
    }
    __syncthreads();
    const float m = fin[0];
    const float r = fin[1];

    for (int i = threadIdx.x; i < WPa; i += TB) {
        d[i] = 0.f;
        d[(HP - 1) * WPa + i] = 0.f;
    }
    for (int h = threadIdx.x; h < H; h += TB) {
        d[(h + 1) * WPa + 3] = 0.f;
        d[(h + 1) * WPa + W + 4] = 0.f;
    }
    #pragma unroll
    for (int k = 0; k < VPT; k++) {
        int j = 4 * (threadIdx.x + k * TB);
        int h = j / W;
        int o = (h + 1) * WPa + 4 + (j - h * W);
        float4 t = v[k];
        t.x = (t.x - m) * r; t.y = (t.y - m) * r;
        t.z = (t.z - m) * r; t.w = (t.w - m) * r;
        if (RELU) {
            t.x = fmaxf(t.x, 0.f); t.y = fmaxf(t.y, 0.f);
            t.z = fmaxf(t.z, 0.f); t.w = fmaxf(t.w, 0.f);
        }
        *reinterpret_cast<float4*>(d + o) = t;
    }
}

// ---------------------------------------------------------------------------
// Warp-per-plane instance norm for small planes (legacy halo-1 layout).
// ---------------------------------------------------------------------------
template<bool RELU, int H, int W, int HP, int WP>
__global__ void inorm_pad_warp(const float* __restrict__ src,
                               float* __restrict__ dst, int nplane)
{
    constexpr int HW  = H * W;
    constexpr int TOT = HP * WP;
    int warp = (blockIdx.x * blockDim.x + threadIdx.x) >> 5;
    int lane = threadIdx.x & 31;
    if (warp >= nplane) return;
    const float* s = src + (size_t)warp * HW;
    float* d = dst + (size_t)warp * TOT;

    float sum = 0.f, ssq = 0.f;
    #pragma unroll
    for (int k = 0; k < (HW + 31) / 32; k++) {
        int i = lane + 32 * k;
        float v = (i < HW) ? __ldg(s + i) : 0.f;
        sum += v;
        ssq += v * v;
    }
    #pragma unroll
    for (int off = 16; off > 0; off >>= 1) {
        sum += __shfl_xor_sync(0xFFFFFFFFu, sum, off);
        ssq += __shfl_xor_sync(0xFFFFFFFFu, ssq, off);
    }
    constexpr float invN = 1.0f / (float)HW;
    float m = sum * invN;
    float var = ssq * invN - m * m;
    float r = rsqrtf(var + 1e-5f);

    #pragma unroll
    for (int k = 0; k < (TOT + 31) / 32; k++) {
        int i = lane + 32 * k;
        if (i < TOT) {
            int h = i / WP, w = i % WP;
            bool in = (h >= 1) && (h <= H) && (w >= 1) && (w <= W);
            float v = 0.f;
            if (in) {
                v = (__ldg(s + (h - 1) * W + (w - 1)) - m) * r;
                if (RELU) v = fmaxf(v, 0.f);
            }
            d[i] = v;
        }
    }
}

// ---------------------------------------------------------------------------
// FC1 with fused maxpool (reads legacy 6x5 padded planes).
// ---------------------------------------------------------------------------
__global__ void fc1_pool_kernel(const float* __restrict__ act,
                                const float* __restrict__ w,
                                const float* __restrict__ bias,
                                float* __restrict__ out)
{
    int b = blockIdx.x;
    int j = threadIdx.x;
    __shared__ float xs[512];
    for (int idx = threadIdx.x; idx < 512; idx += 128) {
        int i = idx & 1;
        int c = idx >> 1;
        const float* p = act + ((size_t)b * 256 + c) * 30;
        int r0 = (2 * i + 1) * 5 + 1;
        int r1 = (2 * i + 2) * 5 + 1;
        xs[idx] = fmaxf(fmaxf(__ldg(p + r0), __ldg(p + r0 + 1)),
                        fmaxf(__ldg(p + r1), __ldg(p + r1 + 1)));
    }
    __syncthreads();
    const float* wr = w + (size_t)j * 512;
    float acc = bias[j];
    #pragma unroll 8
    for (int k = 0; k < 512; k++)
        acc = fmaf(xs[k], __ldg(wr + k), acc);
    out[(size_t)b * 128 + j] = fmaxf(acc, 0.0f);
}

// ---------------------------------------------------------------------------
// FC2: (64,128) @ (50,128)^T + b, tanh -> d_out coor
// ---------------------------------------------------------------------------
__global__ void fc2_kernel(const float* __restrict__ in,
                           const float* __restrict__ w,
                           const float* __restrict__ bias,
                           float* __restrict__ out)
{
    int b = blockIdx.x;
    int j = threadIdx.x;
    if (j >= 50) return;
    const float* x  = in + (size_t)b * 128;
    const float* wr = w  + (size_t)j * 128;
    float acc = bias[j];
    #pragma unroll 8
    for (int k = 0; k < 128; k++)
        acc = fmaf(__ldg(x + k), __ldg(wr + k), acc);
    out[(size_t)b * 50 + j] = tanhf(acc);
}

// ---------------------------------------------------------------------------
// Loss kernel.
// ---------------------------------------------------------------------------
__global__ void loss_kernel(float* __restrict__ out)
{
    const float* pts = out;
    int b = threadIdx.x;
    const float* g = pts + (size_t)b * 50;
    #define G(i, j, comp) g[((i) * 5 + (j)) * 2 + (comp)]

    float rx = 0.f, ry = 0.f, cx = 0.f, cy = 0.f;
    for (int i = 0; i < 5; i++) {
        for (int s = 0; s < 3; s++) {
            #pragma unroll
            for (int comp = 0; comp < 2; comp++) {
                float a0 = G(i, s, comp), a1 = G(i, s + 1, comp), a2 = G(i, s + 2, comp);
                float d0 = (a1 - a0) * (a1 - a0);
                float d1 = (a2 - a1) * (a2 - a1);
                float rv = fmaxf(0.08f, fabsf(d1 - d0));
                if (comp == 0) rx += rv; else ry += rv;
                float c0 = G(s, i, comp), c1 = G(s + 1, i, comp), c2 = G(s + 2, i, comp);
                float e0 = (c1 - c0) * (c1 - c0);
                float e1 = (c2 - c1) * (c2 - c1);
                float cv = fmaxf(0.08f, fabsf(e1 - e0));
                if (comp == 0) cx += cv; else cy += cv;
            }
        }
    }

    __shared__ float sh[4][64];
    sh[0][b] = rx; sh[1][b] = ry; sh[2][b] = cx; sh[3][b] = cy;
    __syncthreads();
    for (int off = 32; off > 0; off >>= 1) {
        if (b < off) {
            sh[0][b] += sh[0][b + off];
            sh[1][b] += sh[1][b + off];
            sh[2][b] += sh[2][b + off];
            sh[3][b] += sh[3][b + off];
        }
        __syncthreads();
    }

    if (b == 0) {
        float inv = 1.0f / 960.0f;
        out[3200] = sh[0][0] * inv;
        out[3201] = sh[1][0] * inv;
        out[3202] = sh[2][0] * inv;
        out[3203] = sh[3][0] * inv;

        const float* g0 = pts;
        #define G0(i, j, comp) g0[((i) * 5 + (j)) * 2 + (comp)]
        float rg = 0.f, cg = 0.f;
        for (int i = 0; i < 5; i++) {
            for (int s = 0; s < 3; s++) {
                {
                    float x0 = G0(i, s, 0),     y0 = G0(i, s, 1);
                    float x1 = G0(i, s + 1, 0), y1 = G0(i, s + 1, 1);
                    float x2 = G0(i, s + 2, 0), y2 = G0(i, s + 2, 1);
                    rg += fabsf((y1 - y0) * (x1 - x2) - (y1 - y2) * (x1 - x0));
                }
                {
                    float x0 = G0(s, i, 0),     y0 = G0(s, i, 1);
                    float x1 = G0(s + 1, i, 0), y1 = G0(s + 1, i, 1);
                    float x2 = G0(s + 2, i, 0), y2 = G0(s + 2, i, 1);
                    cg += fabsf((y1 - y0) * (x1 - x2) - (y1 - y2) * (x1 - x0));
                }
            }
        }
        out[3204] = fmaxf(rg, 0.02f);
        out[3205] = fmaxf(cg, 0.02f);
    }
}

// ---------------------------------------------------------------------------
// Host-side orchestration
// ---------------------------------------------------------------------------
static inline int cdiv(int a, int b) { return (a + b - 1) / b; }

extern "C" void kernel_launch(void* const* d_in, const int* in_sizes, int n_in,
                              void* d_out, int out_size)
{
    (void)in_sizes; (void)n_in; (void)out_size;

    const float* x = (const float*)d_in[0];
    const float* W[8];
    const float* Bi[8];
    for (int i = 0; i < 8; i++) {
        W[i]  = (const float*)d_in[1 + 2 * i];
        Bi[i] = (const float*)d_in[2 + 2 * i];
    }
    const float* fc1_w = (const float*)d_in[17];
    const float* fc1_b = (const float*)d_in[18];
    const float* fc2_w = (const float*)d_in[19];
    const float* fc2_b = (const float*)d_in[20];
    float* out = (float*)d_out;

    float* X;  cudaGetSymbolAddress((void**)&X,  g_bufX);
    float* A;  cudaGetSymbolAddress((void**)&A,  g_bufA);
    float* Bb; cudaGetSymbolAddress((void**)&Bb, g_bufB);
    float* C;  cudaGetSymbolAddress((void**)&C,  g_bufC);
    uint32_t* Whi; cudaGetSymbolAddress((void**)&Whi, g_bufWhi);
    uint32_t* Wlo; cudaGetSymbolAddress((void**)&Wlo, g_bufWlo);

    // ---- pad input (aligned layout 258x200) + L1 weight pre-split
    pad_copy_a<256, 192, 256><<<64 * 5, 256>>>(x, X);
    split_weights_kernel<<<8, 256>>>(W[1], Whi, Wlo);

    // ---- L0 (FFMA, aligned in): conv X->A [bias+relu], inorm A->Bb (130x104)
    {
        dim3 grid(64 * 128 * 96 / 512, 1, 1);
        conv_tiled<4, 2, 5, 258, 200, 3, 8, 128, 96, 8, 5, 1, false, true, true>
            <<<grid, 256>>>(X, W[0], Bi[0], A);
        inorm_pad_reg<false, 128, 96, 256><<<512, 256>>>(A, Bb);
    }
    // ---- L1 (MMA, NTILES=8): Bb->A, inorm A->C (66x56)
    {
        conv_mma<4, 2, 8, 130, 104, 3, 16, 64, 48, 8>
            <<<dim3(384, 1, 1), 256>>>(Bb, Whi, Wlo, A);
        inorm_pad_reg<true, 64, 48, 256><<<1024, 256>>>(A, C);
    }
    // ---- L2 (FFMA, aligned in): C->A, inorm A->Bb (34x32)
    {
        dim3 grid(64 * 32 * 24 / 128, 1, 1);
        conv_tiled<4, 2, 16, 66, 56, 3, 32, 32, 24, 32, 16, 1, false, false, false>
            <<<grid, 256>>>(C, W[2], nullptr, A);
        inorm_pad_reg<true, 32, 24, 64><<<2048, 64>>>(A, Bb);
    }
    // ---- L3 (FFMA, aligned in): Z=2 atomic; Bb->A, inorm A->C (legacy 18x14)
    {
        cudaMemsetAsync(A, 0, (size_t)64 * 64 * 16 * 12 * sizeof(float));
        dim3 grid(64 * 16 * 12 / 128, 2, 2);
        conv_tiled<4, 2, 32, 34, 32, 3, 64, 16, 12, 32, 16, 2, true, false, false>
            <<<grid, 256>>>(Bb, W[3], nullptr, A);
        inorm_pad_warp<true, 16, 12, 18, 14><<<512, 256>>>(A, C, 64 * 64);
    }
    // ---- L4 (FFMA, legacy in): Z=4 atomic; C->A, inorm A->Bb (10x8)
    {
        cudaMemsetAsync(A, 0, (size_t)64 * 128 * 8 * 6 * sizeof(float));
        dim3 grid(64 * 8 * 6 / 128, 4, 4);
        conv_tiled<4, 2, 64, 18, 14, 0, 128, 8, 6, 32, 16, 4, true, false, false>
            <<<grid, 256>>>(C, W[4], nullptr, A);
        inorm_pad_warp<true, 8, 6, 10, 8><<<1024, 256>>>(A, Bb, 64 * 128);
    }
    // ---- L5 (FFMA, legacy in): Z=8 atomic; Bb->A, inorm A->C (6x5)
    {
        cudaMemsetAsync(A, 0, (size_t)64 * 256 * 4 * 3 * sizeof(float));
        dim3 grid(6, 8, 8);
        conv_tiled<4, 2, 128, 10, 8, 0, 256, 4, 3, 32, 16, 8, true, false, false>
            <<<grid, 256>>>(Bb, W[5], nullptr, A);
        inorm_pad_warp<true, 4, 3, 6, 5><<<2048, 256>>>(A, C, 64 * 256);
    }
    // ---- L6 (FFMA, legacy in): K=3, Z=8 atomic; C->A, inorm A->Bb
    {
        cudaMemsetAsync(A, 0, (size_t)64 * 256 * 4 * 3 * sizeof(float));
        dim3 grid(6, 8, 8);
        conv_tiled<3, 1, 256, 6, 5, 0, 256, 4, 3, 32, 32, 8, true, false, false>
            <<<grid, 256>>>(C, W[6], nullptr, A);
        inorm_pad_warp<true, 4, 3, 6, 5><<<2048, 256>>>(A, Bb, 64 * 256);
    }
    // ---- L7 (FFMA, legacy in): same; Bb->A, inorm A->C
    {
        cudaMemsetAsync(A, 0, (size_t)64 * 256 * 4 * 3 * sizeof(float));
        dim3 grid(6, 8, 8);
        conv_tiled<3, 1, 256, 6, 5, 0, 256, 4, 3, 32, 32, 8, true, false, false>
            <<<grid, 256>>>(Bb, W[7], nullptr, A);
        inorm_pad_warp<true, 4, 3, 6, 5><<<2048, 256>>>(A, C, 64 * 256);
    }

    // ---- fused maxpool + FC1: C (legacy padded) -> A (64,128)
    fc1_pool_kernel<<<64, 128>>>(C, fc1_w, fc1_b, A);
    // ---- FC2 + tanh: A -> out[0..3199]
    fc2_kernel<<<64, 64>>>(A, fc2_w, fc2_b, out);
    // ---- losses
    loss_kernel<<<1, 64>>>(out);
}

// round 14
// speedup vs baseline: 1.5304x; 1.0101x over previous
#include <cuda_runtime.h>
#include <math.h>
#include <stdint.h>

// ---------------------------------------------------------------------------
// Scratch buffers
// ---------------------------------------------------------------------------
__device__ __align__(256) float g_bufX[16600000];   // padded input 64*5*258*200
__device__ __align__(256) float g_bufA[6400000];    // unpadded conv outputs
__device__ __align__(256) float g_bufB[7000000];    // padded activations
__device__ __align__(256) float g_bufC[7000000];    // padded activations
// tf32-split weights: L1@0 (2048), L2@2048 (8192)
__device__ __align__(256) uint32_t g_bufWhi[10240];
__device__ __align__(256) uint32_t g_bufWlo[10240];

// ---------------------------------------------------------------------------
// tf32 helpers
// ---------------------------------------------------------------------------
__device__ __forceinline__ uint32_t f2tf32(float x) {
    uint32_t r;
    asm("cvt.rna.tf32.f32 %0, %1;" : "=r"(r) : "f"(x));
    return r;
}
__device__ __forceinline__ void tf32split(float x, uint32_t& hi, uint32_t& lo) {
    hi = f2tf32(x);
    float r = x - __uint_as_float(hi);
    lo = f2tf32(r);
}
__device__ __forceinline__ void mma_tf32(float d[4],
                                         uint32_t a0, uint32_t a1, uint32_t a2, uint32_t a3,
                                         uint32_t b0, uint32_t b1) {
    asm volatile(
        "mma.sync.aligned.m16n8k8.row.col.f32.tf32.tf32.f32 "
        "{%0,%1,%2,%3}, {%4,%5,%6,%7}, {%8,%9}, {%0,%1,%2,%3};"
        : "+f"(d[0]), "+f"(d[1]), "+f"(d[2]), "+f"(d[3])
        : "r"(a0), "r"(a1), "r"(a2), "r"(a3), "r"(b0), "r"(b1));
}

__global__ void split_one_kernel(const float* __restrict__ w,
                                 uint32_t* __restrict__ hi,
                                 uint32_t* __restrict__ lo, int n)
{
    int i = blockIdx.x * blockDim.x + threadIdx.x;
    if (i >= n) return;
    uint32_t h, l;
    tf32split(w[i], h, l);
    hi[i] = h;
    lo[i] = l;
}

// ---------------------------------------------------------------------------
// ALIGNED padded layout: left pad 4, right pad 4 -> WPa = W+8 (mult of 4).
// ---------------------------------------------------------------------------
template<int H, int W, int TB>
__global__ void __launch_bounds__(TB)
pad_copy_a(const float* __restrict__ src, float* __restrict__ dst)
{
    static_assert(W % 4 == 0, "");
    constexpr int WPa = W + 8;
    constexpr int HP  = H + 2;
    const float4* s4 = reinterpret_cast<const float4*>(src + (size_t)blockIdx.x * (H * W));
    float* d = dst + (size_t)blockIdx.x * (HP * WPa);

    for (int i = threadIdx.x; i < WPa; i += TB) {
        d[i] = 0.f;
        d[(HP - 1) * WPa + i] = 0.f;
    }
    for (int h = threadIdx.x; h < H; h += TB) {
        d[(h + 1) * WPa + 3] = 0.f;
        d[(h + 1) * WPa + W + 4] = 0.f;
    }
    constexpr int N4 = H * W / 4;
    for (int q = threadIdx.x; q < N4; q += TB) {
        int j = 4 * q;
        int h = j / W;
        int o = (h + 1) * WPa + 4 + (j - h * W);
        *reinterpret_cast<float4*>(d + o) = __ldg(s4 + q);
    }
}

// ---------------------------------------------------------------------------
// FFMA conv. LOFF = left offset of readable halo (3 aligned / 0 legacy).
// ---------------------------------------------------------------------------
template<int K, int S, int CIN, int HP, int WP, int LOFF,
         int COUT, int HOUT, int WOUT,
         int CO_T, int CI_T, int ZSPLIT, bool ATOMIC, bool BIAS, bool RELU>
__global__ void __launch_bounds__(256)
conv_tiled(const float* __restrict__ in,
           const float* __restrict__ w,
           const float* __restrict__ bias,
           float* __restrict__ out)
{
    constexpr int CO_M = 4, PIX_M = 4;
    constexpr int G    = CO_T / CO_M;
    constexpr int PTH  = 256 / G;
    constexpr int PIXB = PTH * PIX_M;
    constexpr int KK   = K * K;
    constexpr int WPITCH = CI_T * KK + 1;
    constexpr int HW   = HOUT * WOUT;
    constexpr int NT   = 64 * HW;
    constexpr int PSZ  = HP * WP;
    static_assert(CIN / ZSPLIT == CI_T, "one smem weight tile per block");

    __shared__ float sw[CO_T * WPITCH];

    const int tco  = threadIdx.x % G;
    const int tpix = threadIdx.x / G;
    const int co0  = blockIdx.y * CO_T;
    const int nbase = blockIdx.x * PIXB;
    const int ci_begin = blockIdx.z * CI_T;

    {
        const int tot = CO_T * CI_T * KK;
        const float* wsrc = w + ((long)co0 * CIN + ci_begin) * KK;
        for (int idx = threadIdx.x; idx < tot; idx += 256) {
            int c = idx / (CI_T * KK);
            int r = idx % (CI_T * KK);
            sw[c * WPITCH + r] = wsrc[(long)c * CIN * KK + r];
        }
    }
    __syncthreads();

    int nidx[PIX_M];
    const float* pci[PIX_M];
    #pragma unroll
    for (int p = 0; p < PIX_M; p++) {
        int n = nbase + p * PTH + tpix;
        nidx[p] = n;
        int nn = (n < NT) ? n : 0;
        int b  = nn / HW;
        int hw = nn % HW;
        int ho = hw / WOUT, wo = hw % WOUT;
        pci[p] = in + ((long)b * CIN + ci_begin) * PSZ + (ho * S) * WP + (wo * S) + LOFF;
    }

    float acc[CO_M][PIX_M];
    #pragma unroll
    for (int m = 0; m < CO_M; m++)
        #pragma unroll
        for (int p = 0; p < PIX_M; p++) acc[m][p] = 0.f;

    const float* wrow0 = &sw[(tco * CO_M) * WPITCH];
    for (int ci = 0; ci < CI_T; ci++) {
        const float* wrow = wrow0 + ci * KK;
        #pragma unroll
        for (int kh = 0; kh < K; kh++) {
            #pragma unroll
            for (int kw = 0; kw < K; kw++) {
                float iv[PIX_M];
                #pragma unroll
                for (int p = 0; p < PIX_M; p++)
                    iv[p] = __ldg(pci[p] + kh * WP + kw);
                float wv[CO_M];
                #pragma unroll
                for (int m = 0; m < CO_M; m++)
                    wv[m] = wrow[m * WPITCH + kh * K + kw];
                #pragma unroll
                for (int m = 0; m < CO_M; m++)
                    #pragma unroll
                    for (int p = 0; p < PIX_M; p++)
                        acc[m][p] = fmaf(wv[m], iv[p], acc[m][p]);
            }
        }
        #pragma unroll
        for (int p = 0; p < PIX_M; p++) pci[p] += PSZ;
    }

    #pragma unroll
    for (int p = 0; p < PIX_M; p++) {
        int n = nidx[p];
        if (n >= NT) continue;
        int b = n / HW, hw = n % HW;
        #pragma unroll
        for (int m = 0; m < CO_M; m++) {
            int co = co0 + tco * CO_M + m;
            long oidx = ((long)b * COUT + co) * HW + hw;
            if (ATOMIC) {
                atomicAdd(out + oidx, acc[m][p]);
            } else {
                float v = acc[m][p] + (BIAS ? bias[co] : 0.f);
                if (RELU) v = fmaxf(v, 0.f);
                out[oidx] = v;
            }
        }
    }
}

// ---------------------------------------------------------------------------
// Tensor-core conv, tf32 3x-split, pre-split weights. Full K, non-atomic.
// ---------------------------------------------------------------------------
template<int K, int S, int CIN, int HP, int WP, int LOFF,
         int COUT, int HOUT, int WOUT, int NTILES>
__global__ void __launch_bounds__(256)
conv_mma(const float* __restrict__ in,
         const uint32_t* __restrict__ whi,
         const uint32_t* __restrict__ wlo,
         float* __restrict__ out)
{
    constexpr int KK    = K * K;
    constexpr int KTOT  = CIN * KK;
    constexpr int HW    = HOUT * WOUT;
    constexpr int PSZ   = HP * WP;

    const int warp = threadIdx.x >> 5;
    const int lane = threadIdx.x & 31;
    const int gid  = lane >> 2;
    const int tig  = lane & 3;

    const int co0  = blockIdx.y * 16;
    const int pix0 = (blockIdx.x * 8 + warp) * (NTILES * 8);

    const uint32_t* ph0 = whi + (size_t)(co0 + gid) * KTOT;
    const uint32_t* ph1 = ph0 + (size_t)8 * KTOT;
    const uint32_t* pl0 = wlo + (size_t)(co0 + gid) * KTOT;
    const uint32_t* pl1 = pl0 + (size_t)8 * KTOT;

    const float* pb[NTILES];
    #pragma unroll
    for (int t = 0; t < NTILES; t++) {
        int p  = pix0 + t * 8 + gid;
        int b  = p / HW, hw = p % HW;
        int ho = hw / WOUT, wo = hw % WOUT;
        pb[t] = in + (size_t)b * CIN * PSZ + (ho * S) * WP + (wo * S) + LOFF;
    }

    float d[NTILES][4];
    #pragma unroll
    for (int t = 0; t < NTILES; t++)
        #pragma unroll
        for (int i = 0; i < 4; i++) d[t][i] = 0.f;

    #pragma unroll 2
    for (int kc = 0; kc < KTOT / 8; kc++) {
        const int k0 = kc * 8 + tig;
        const int k1 = k0 + 4;
        int ci0 = k0 / KK, t0 = k0 % KK;
        int ci1 = k1 / KK, t1 = k1 % KK;
        int off0 = ci0 * PSZ + (t0 / K) * WP + (t0 % K);
        int off1 = ci1 * PSZ + (t1 / K) * WP + (t1 % K);

        uint32_t ah0 = __ldg(ph0 + k0);
        uint32_t ah2 = __ldg(ph0 + k1);
        uint32_t ah1 = __ldg(ph1 + k0);
        uint32_t ah3 = __ldg(ph1 + k1);
        uint32_t al0 = __ldg(pl0 + k0);
        uint32_t al2 = __ldg(pl0 + k1);
        uint32_t al1 = __ldg(pl1 + k0);
        uint32_t al3 = __ldg(pl1 + k1);

        #pragma unroll
        for (int t = 0; t < NTILES; t++) {
            float b0 = __ldg(pb[t] + off0);
            float b1 = __ldg(pb[t] + off1);
            uint32_t bh0, bl0, bh1, bl1;
            tf32split(b0, bh0, bl0);
            tf32split(b1, bh1, bl1);
            mma_tf32(d[t], ah0, ah1, ah2, ah3, bh0, bh1);
            mma_tf32(d[t], ah0, ah1, ah2, ah3, bl0, bl1);
            mma_tf32(d[t], al0, al1, al2, al3, bh0, bh1);
        }
    }

    #pragma unroll
    for (int t = 0; t < NTILES; t++) {
        #pragma unroll
        for (int cc = 0; cc < 2; cc++) {
            int p  = pix0 + t * 8 + 2 * tig + cc;
            int b  = p / HW, hw = p % HW;
            long base = ((long)b * COUT) * HW + hw;
            out[base + (long)(co0 + gid) * HW]     = d[t][cc];
            out[base + (long)(co0 + gid + 8) * HW] = d[t][cc + 2];
        }
    }
}

// ---------------------------------------------------------------------------
// Single-pass register-resident instance norm -> ALIGNED padded output.
// ---------------------------------------------------------------------------
template<bool RELU, int H, int W, int TB>
__global__ void __launch_bounds__(TB)
inorm_pad_reg(const float* __restrict__ src, float* __restrict__ dst)
{
    static_assert(W % 4 == 0, "");
    constexpr int WPa = W + 8;
    constexpr int HP  = H + 2;
    constexpr int HW  = H * W;
    constexpr int N4  = HW / 4;
    static_assert(N4 % TB == 0, "exact tiling");
    constexpr int VPT = N4 / TB;
    constexpr int NW  = TB / 32;

    const float4* s4 = reinterpret_cast<const float4*>(src + (size_t)blockIdx.x * HW);
    float* d = dst + (size_t)blockIdx.x * (HP * WPa);

    float4 v[VPT];
    float sum = 0.f, ssq = 0.f;
    #pragma unroll
    for (int k = 0; k < VPT; k++) {
        float4 t = __ldg(s4 + threadIdx.x + k * TB);
        v[k] = t;
        sum += (t.x + t.y) + (t.z + t.w);
        ssq += t.x * t.x + t.y * t.y + t.z * t.z + t.w * t.w;
    }
    #pragma unroll
    for (int off = 16; off > 0; off >>= 1) {
        sum += __shfl_xor_sync(0xFFFFFFFFu, sum, off);
        ssq += __shfl_xor_sync(0xFFFFFFFFu, ssq, off);
    }
    __shared__ float shs[NW], shq[NW], fin[2];
    if ((threadIdx.x & 31) == 0) {
        shs[threadIdx.x >> 5] = sum;
        shq[threadIdx.x >> 5] = ssq;
    }
    __syncthreads();
    if (threadIdx.x == 0) {
        float s = 0.f, q = 0.f;
        #pragma unroll
        for (int i = 0; i < NW; i++) { s += shs[i]; q += shq[i]; }
        constexpr float invN = 1.0f / (float)HW;
        float m = s * invN;
        float var = q * invN - m * m;
        fin[0] = m;
        fin[1] = rsqrtf(var + 1e-5f);
    }
    __syncthreads();
    const float m = fin[0];
    const float r = fin[1];

    for (int i = threadIdx.x; i < WPa; i += TB) {
        d[i] = 0.f;
        d[(HP - 1) * WPa + i] = 0.f;
    }
    for (int h = threadIdx.x; h < H; h += TB) {
        d[(h + 1) * WPa + 3] = 0.f;
        d[(h + 1) * WPa + W + 4] = 0.f;
    }
    #pragma unroll
    for (int k = 0; k < VPT; k++) {
        int j = 4 * (threadIdx.x + k * TB);
        int h = j / W;
        int o = (h + 1) * WPa + 4 + (j - h * W);
        float4 t = v[k];
        t.x = (t.x - m) * r; t.y = (t.y - m) * r;
        t.z = (t.z - m) * r; t.w = (t.w - m) * r;
        if (RELU) {
            t.x = fmaxf(t.x, 0.f); t.y = fmaxf(t.y, 0.f);
            t.z = fmaxf(t.z, 0.f); t.w = fmaxf(t.w, 0.f);
        }
        *reinterpret_cast<float4*>(d + o) = t;
    }
}

// ---------------------------------------------------------------------------
// Warp-per-plane instance norm for small planes (legacy halo-1 layout).
// ---------------------------------------------------------------------------
template<bool RELU, int H, int W, int HP, int WP>
__global__ void inorm_pad_warp(const float* __restrict__ src,
                               float* __restrict__ dst, int nplane)
{
    constexpr int HW  = H * W;
    constexpr int TOT = HP * WP;
    int warp = (blockIdx.x * blockDim.x + threadIdx.x) >> 5;
    int lane = threadIdx.x & 31;
    if (warp >= nplane) return;
    const float* s = src + (size_t)warp * HW;
    float* d = dst + (size_t)warp * TOT;

    float sum = 0.f, ssq = 0.f;
    #pragma unroll
    for (int k = 0; k < (HW + 31) / 32; k++) {
        int i = lane + 32 * k;
        float v = (i < HW) ? __ldg(s + i) : 0.f;
        sum += v;
        ssq += v * v;
    }
    #pragma unroll
    for (int off = 16; off > 0; off >>= 1) {
        sum += __shfl_xor_sync(0xFFFFFFFFu, sum, off);
        ssq += __shfl_xor_sync(0xFFFFFFFFu, ssq, off);
    }
    constexpr float invN = 1.0f / (float)HW;
    float m = sum * invN;
    float var = ssq * invN - m * m;
    float r = rsqrtf(var + 1e-5f);

    #pragma unroll
    for (int k = 0; k < (TOT + 31) / 32; k++) {
        int i = lane + 32 * k;
        if (i < TOT) {
            int h = i / WP, w = i % WP;
            bool in = (h >= 1) && (h <= H) && (w >= 1) && (w <= W);
            float v = 0.f;
            if (in) {
                v = (__ldg(s + (h - 1) * W + (w - 1)) - m) * r;
                if (RELU) v = fmaxf(v, 0.f);
            }
            d[i] = v;
        }
    }
}

// ---------------------------------------------------------------------------
// FC1 with fused maxpool (reads legacy 6x5 padded planes).
// ---------------------------------------------------------------------------
__global__ void fc1_pool_kernel(const float* __restrict__ act,
                                const float* __restrict__ w,
                                const float* __restrict__ bias,
                                float* __restrict__ out)
{
    int b = blockIdx.x;
    int j = threadIdx.x;
    __shared__ float xs[512];
    for (int idx = threadIdx.x; idx < 512; idx += 128) {
        int i = idx & 1;
        int c = idx >> 1;
        const float* p = act + ((size_t)b * 256 + c) * 30;
        int r0 = (2 * i + 1) * 5 + 1;
        int r1 = (2 * i + 2) * 5 + 1;
        xs[idx] = fmaxf(fmaxf(__ldg(p + r0), __ldg(p + r0 + 1)),
                        fmaxf(__ldg(p + r1), __ldg(p + r1 + 1)));
    }
    __syncthreads();
    const float* wr = w + (size_t)j * 512;
    float acc = bias[j];
    #pragma unroll 8
    for (int k = 0; k < 512; k++)
        acc = fmaf(xs[k], __ldg(wr + k), acc);
    out[(size_t)b * 128 + j] = fmaxf(acc, 0.0f);
}

// ---------------------------------------------------------------------------
// FC2: (64,128) @ (50,128)^T + b, tanh -> d_out coor
// ---------------------------------------------------------------------------
__global__ void fc2_kernel(const float* __restrict__ in,
                           const float* __restrict__ w,
                           const float* __restrict__ bias,
                           float* __restrict__ out)
{
    int b = blockIdx.x;
    int j = threadIdx.x;
    if (j >= 50) return;
    const float* x  = in + (size_t)b * 128;
    const float* wr = w  + (size_t)j * 128;
    float acc = bias[j];
    #pragma unroll 8
    for (int k = 0; k < 128; k++)
        acc = fmaf(__ldg(x + k), __ldg(wr + k), acc);
    out[(size_t)b * 50 + j] = tanhf(acc);
}

// ---------------------------------------------------------------------------
// Loss kernel.
// ---------------------------------------------------------------------------
__global__ void loss_kernel(float* __restrict__ out)
{
    const float* pts = out;
    int b = threadIdx.x;
    const float* g = pts + (size_t)b * 50;
    #define G(i, j, comp) g[((i) * 5 + (j)) * 2 + (comp)]

    float rx = 0.f, ry = 0.f, cx = 0.f, cy = 0.f;
    for (int i = 0; i < 5; i++) {
        for (int s = 0; s < 3; s++) {
            #pragma unroll
            for (int comp = 0; comp < 2; comp++) {
                float a0 = G(i, s, comp), a1 = G(i, s + 1, comp), a2 = G(i, s + 2, comp);
                float d0 = (a1 - a0) * (a1 - a0);
                float d1 = (a2 - a1) * (a2 - a1);
                float rv = fmaxf(0.08f, fabsf(d1 - d0));
                if (comp == 0) rx += rv; else ry += rv;
                float c0 = G(s, i, comp), c1 = G(s + 1, i, comp), c2 = G(s + 2, i, comp);
                float e0 = (c1 - c0) * (c1 - c0);
                float e1 = (c2 - c1) * (c2 - c1);
                float cv = fmaxf(0.08f, fabsf(e1 - e0));
                if (comp == 0) cx += cv; else cy += cv;
            }
        }
    }

    __shared__ float sh[4][64];
    sh[0][b] = rx; sh[1][b] = ry; sh[2][b] = cx; sh[3][b] = cy;
    __syncthreads();
    for (int off = 32; off > 0; off >>= 1) {
        if (b < off) {
            sh[0][b] += sh[0][b + off];
            sh[1][b] += sh[1][b + off];
            sh[2][b] += sh[2][b + off];
            sh[3][b] += sh[3][b + off];
        }
        __syncthreads();
    }

    if (b == 0) {
        float inv = 1.0f / 960.0f;
        out[3200] = sh[0][0] * inv;
        out[3201] = sh[1][0] * inv;
        out[3202] = sh[2][0] * inv;
        out[3203] = sh[3][0] * inv;

        const float* g0 = pts;
        #define G0(i, j, comp) g0[((i) * 5 + (j)) * 2 + (comp)]
        float rg = 0.f, cg = 0.f;
        for (int i = 0; i < 5; i++) {
            for (int s = 0; s < 3; s++) {
                {
                    float x0 = G0(i, s, 0),     y0 = G0(i, s, 1);
                    float x1 = G0(i, s + 1, 0), y1 = G0(i, s + 1, 1);
                    float x2 = G0(i, s + 2, 0), y2 = G0(i, s + 2, 1);
                    rg += fabsf((y1 - y0) * (x1 - x2) - (y1 - y2) * (x1 - x0));
                }
                {
                    float x0 = G0(s, i, 0),     y0 = G0(s, i, 1);
                    float x1 = G0(s + 1, i, 0), y1 = G0(s + 1, i, 1);
                    float x2 = G0(s + 2, i, 0), y2 = G0(s + 2, i, 1);
                    cg += fabsf((y1 - y0) * (x1 - x2) - (y1 - y2) * (x1 - x0));
                }
            }
        }
        out[3204] = fmaxf(rg, 0.02f);
        out[3205] = fmaxf(cg, 0.02f);
    }
}

// ---------------------------------------------------------------------------
// Host-side orchestration
// ---------------------------------------------------------------------------
static inline int cdiv(int a, int b) { return (a + b - 1) / b; }

extern "C" void kernel_launch(void* const* d_in, const int* in_sizes, int n_in,
                              void* d_out, int out_size)
{
    (void)in_sizes; (void)n_in; (void)out_size;

    const float* x = (const float*)d_in[0];
    const float* W[8];
    const float* Bi[8];
    for (int i = 0; i < 8; i++) {
        W[i]  = (const float*)d_in[1 + 2 * i];
        Bi[i] = (const float*)d_in[2 + 2 * i];
    }
    const float* fc1_w = (const float*)d_in[17];
    const float* fc1_b = (const float*)d_in[18];
    const float* fc2_w = (const float*)d_in[19];
    const float* fc2_b = (const float*)d_in[20];
    float* out = (float*)d_out;

    float* X;  cudaGetSymbolAddress((void**)&X,  g_bufX);
    float* A;  cudaGetSymbolAddress((void**)&A,  g_bufA);
    float* Bb; cudaGetSymbolAddress((void**)&Bb, g_bufB);
    float* C;  cudaGetSymbolAddress((void**)&C,  g_bufC);
    uint32_t* Whi; cudaGetSymbolAddress((void**)&Whi, g_bufWhi);
    uint32_t* Wlo; cudaGetSymbolAddress((void**)&Wlo, g_bufWlo);

    // ---- pad input (aligned 258x200) + pre-split W1, W2
    pad_copy_a<256, 192, 256><<<64 * 5, 256>>>(x, X);
    split_one_kernel<<<cdiv(2048, 256), 256>>>(W[1], Whi, Wlo, 2048);
    split_one_kernel<<<cdiv(8192, 256), 256>>>(W[2], Whi + 2048, Wlo + 2048, 8192);

    // ---- L0 (FFMA, aligned in): conv X->A [bias+relu], inorm A->Bb (130x104)
    {
        dim3 grid(64 * 128 * 96 / 512, 1, 1);
        conv_tiled<4, 2, 5, 258, 200, 3, 8, 128, 96, 8, 5, 1, false, true, true>
            <<<grid, 256>>>(X, W[0], Bi[0], A);
        inorm_pad_reg<false, 128, 96, 256><<<512, 256>>>(A, Bb);
    }
    // ---- L1 (MMA, NTILES=8): Bb->A, inorm A->C (66x56)
    {
        conv_mma<4, 2, 8, 130, 104, 3, 16, 64, 48, 8>
            <<<dim3(384, 1, 1), 256>>>(Bb, Whi, Wlo, A);
        inorm_pad_reg<true, 64, 48, 256><<<1024, 256>>>(A, C);
    }
    // ---- L2 (MMA, NTILES=8): C->A, inorm A->Bb (34x32)
    {
        conv_mma<4, 2, 16, 66, 56, 3, 32, 32, 24, 8>
            <<<dim3(96, 2, 1), 256>>>(C, Whi + 2048, Wlo + 2048, A);
        inorm_pad_reg<true, 32, 24, 64><<<2048, 64>>>(A, Bb);
    }
    // ---- L3 (FFMA, aligned in): Z=2 atomic; Bb->A, inorm A->C (legacy 18x14)
    {
        cudaMemsetAsync(A, 0, (size_t)64 * 64 * 16 * 12 * sizeof(float));
        dim3 grid(64 * 16 * 12 / 128, 2, 2);
        conv_tiled<4, 2, 32, 34, 32, 3, 64, 16, 12, 32, 16, 2, true, false, false>
            <<<grid, 256>>>(Bb, W[3], nullptr, A);
        inorm_pad_warp<true, 16, 12, 18, 14><<<512, 256>>>(A, C, 64 * 64);
    }
    // ---- L4 (FFMA, legacy in): Z=4 atomic; C->A, inorm A->Bb (10x8)
    {
        cudaMemsetAsync(A, 0, (size_t)64 * 128 * 8 * 6 * sizeof(float));
        dim3 grid(64 * 8 * 6 / 128, 4, 4);
        conv_tiled<4, 2, 64, 18, 14, 0, 128, 8, 6, 32, 16, 4, true, false, false>
            <<<grid, 256>>>(C, W[4], nullptr, A);
        inorm_pad_warp<true, 8, 6, 10, 8><<<1024, 256>>>(A, Bb, 64 * 128);
    }
    // ---- L5 (FFMA, legacy in): Z=8 atomic; Bb->A, inorm A->C (6x5)
    {
        cudaMemsetAsync(A, 0, (size_t)64 * 256 * 4 * 3 * sizeof(float));
        dim3 grid(6, 8, 8);
        conv_tiled<4, 2, 128, 10, 8, 0, 256, 4, 3, 32, 16, 8, true, false, false>
            <<<grid, 256>>>(Bb, W[5], nullptr, A);
        inorm_pad_warp<true, 4, 3, 6, 5><<<2048, 256>>>(A, C, 64 * 256);
    }
    // ---- L6 (FFMA, legacy in): K=3, Z=8 atomic; C->A, inorm A->Bb
    {
        cudaMemsetAsync(A, 0, (size_t)64 * 256 * 4 * 3 * sizeof(float));
        dim3 grid(6, 8, 8);
        conv_tiled<3, 1, 256, 6, 5, 0, 256, 4, 3, 32, 32, 8, true, false, false>
            <<<grid, 256>>>(C, W[6], nullptr, A);
        inorm_pad_warp<true, 4, 3, 6, 5><<<2048, 256>>>(A, Bb, 64 * 256);
    }
    // ---- L7 (FFMA, legacy in): same; Bb->A, inorm A->C
    {
        cudaMemsetAsync(A, 0, (size_t)64 * 256 * 4 * 3 * sizeof(float));
        dim3 grid(6, 8, 8);
        conv_tiled<3, 1, 256, 6, 5, 0, 256, 4, 3, 32, 32, 8, true, false, false>
            <<<grid, 256>>>(Bb, W[7], nullptr, A);
        inorm_pad_warp<true, 4, 3, 6, 5><<<2048, 256>>>(A, C, 64 * 256);
    }

    // ---- fused maxpool + FC1: C (legacy padded) -> A (64,128)
    fc1_pool_kernel<<<64, 128>>>(C, fc1_w, fc1_b, A);
    // ---- FC2 + tanh: A -> out[0..3199]
    fc2_kernel<<<64, 64>>>(A, fc2_w, fc2_b, out);
    // ---- losses
    loss_kernel<<<1, 64>>>(out);
}